// round 11
// baseline (speedup 1.0000x reference)
#include <cuda_runtime.h>
#include <cuda_bf16.h>
#include <cstdint>
#include <math.h>

#define S   2048
#define H   2048
#define ROOM 256
#define NH  16
#define HD  128
#define SCALE 0.08838834764831845f  // 1/sqrt(128)

typedef __nv_bfloat16 bf16;

// ---------------- device globals (allocation-free scratch, ~72MB) ----------
__device__ __align__(16) bf16 g_Hh [(size_t)S*H],    g_Hl [(size_t)S*H];     // hidden planes
__device__ __align__(16) bf16 g_QBh[(size_t)H*H],    g_QBl[(size_t)H*H];     // q_block planes (ungathered)
__device__ __align__(16) bf16 g_KBh[(size_t)ROOM*H], g_KBl[(size_t)ROOM*H];  // k_block planes
__device__ __align__(16) bf16 g_VBh[(size_t)ROOM*H], g_VBl[(size_t)ROOM*H];  // v_block planes
__device__ __align__(16) bf16 g_Qh [(size_t)S*H],    g_Ql [(size_t)S*H];     // Q projection planes
__device__ __align__(16) bf16 g_Kh [(size_t)S*ROOM], g_Kl [(size_t)S*ROOM];  // k_one planes
__device__ float g_V[(size_t)S * ROOM];  // v_one fp32 (round-6 AV path)
__device__ float g_A[(size_t)S * H];     // attn_out fp32
__device__ int   g_rooms[8];

// ---------------- helpers ----------------
__device__ __forceinline__ void split2(float2 v, unsigned &h, unsigned &l)
{
    bf16 h0 = __float2bfloat16_rn(v.x);
    bf16 h1 = __float2bfloat16_rn(v.y);
    float r0 = v.x - __bfloat162float(h0);
    float r1 = v.y - __bfloat162float(h1);
    bf16 l0 = __float2bfloat16_rn(r0);
    bf16 l1 = __float2bfloat16_rn(r1);
    h = ((unsigned)__bfloat16_as_ushort(h1) << 16) | __bfloat16_as_ushort(h0);
    l = ((unsigned)__bfloat16_as_ushort(l1) << 16) | __bfloat16_as_ushort(l0);
}
__device__ __forceinline__ void split1(float x, bf16& h, bf16& l) {
    h = __float2bfloat16_rn(x);
    l = __float2bfloat16_rn(x - __bfloat162float(h));
}
__device__ __forceinline__ unsigned pack2(bf16 a, bf16 b) {
    return ((unsigned)__bfloat16_as_ushort(b) << 16) | __bfloat16_as_ushort(a);
}
__device__ __forceinline__ void mma16816(float* d, const unsigned* a, const unsigned* b)
{
    asm volatile(
        "mma.sync.aligned.m16n8k16.row.col.f32.bf16.bf16.f32 "
        "{%0,%1,%2,%3}, {%4,%5,%6,%7}, {%8,%9}, {%0,%1,%2,%3};\n"
        : "+f"(d[0]), "+f"(d[1]), "+f"(d[2]), "+f"(d[3])
        : "r"(a[0]), "r"(a[1]), "r"(a[2]), "r"(a[3]), "r"(b[0]), "r"(b[1]));
}

// ---------------------------------------------------------------------------
// PLANE-INPUT NT GEMM (round-6 proven NT path; only the loads changed from
// fp32+split to pre-split u32 plane loads at the same offsets).
// C[128,128] = A[M,K] @ B[N,K]^T, 3-term split, fp32 accum. 256 thr, BK=32.
// GATHER: 256-row-block gather on B's n rows. SPLITOUT: write bf16 planes.
// ---------------------------------------------------------------------------
template<bool GATHER, bool SPLITOUT>
__device__ __forceinline__ void nt_planes(
    const bf16* __restrict__ Ah, const bf16* __restrict__ Al, int lda,
    const bf16* __restrict__ Bh, const bf16* __restrict__ Bl, int ldb,
    int K, int m0, int n0, float scale,
    float* __restrict__ Cf, bf16* __restrict__ Ch, bf16* __restrict__ Cl, int ldc)
{
    __shared__ unsigned sAh[2048], sAl[2048], sBh[2048], sBl[2048];
    const int tid = threadIdx.x;
    const int ln  = tid & 31;
    const int warp = tid >> 5;
    const int wm = warp >> 2, wn = warp & 3;

    // ---- staging precompute (identical indexing to round 6) ----
    int a_soff[8], a_goff[8], b_soff[8], b_goff[8];
#pragma unroll
    for (int i = 0; i < 8; i++) {
        int linear = tid + 256 * i;            // 0..2047 pairs
        int r = linear >> 4, c = (linear & 15) * 2;
        int rr = r & 15, cc = c & 15;
        a_soff[i] = (((r >> 4) * 2 + (c >> 4)) * 32
                     + (rr & 7) * 4 + ((cc & 7) >> 1)) * 4
                    + ((rr >> 3) | ((cc >> 3) << 1));
        a_goff[i] = (m0 + r) * lda + c;

        int nn = linear >> 4, kk = (linear & 15) * 2;
        int k16 = kk & 15;
        b_soff[i] = (((nn >> 3) * 2 + (kk >> 4)) * 32
                     + (nn & 7) * 4 + ((k16 & 7) >> 1)) * 2
                    + (k16 >> 3);
        int row = n0 + nn;
        if (GATHER) row = g_rooms[row >> 8] * ROOM + (row & 255);
        b_goff[i] = row * ldb + kk;
    }

    float acc[4][4][4];
#pragma unroll
    for (int i = 0; i < 4; i++)
#pragma unroll
        for (int j = 0; j < 4; j++)
#pragma unroll
            for (int r = 0; r < 4; r++) acc[i][j][r] = 0.f;

    unsigned pah[8], pal[8], pbh[8], pbl[8];

    // ---- preload chunk 0 ----
#pragma unroll
    for (int i = 0; i < 8; i++) {
        pah[i] = *(const unsigned*)(Ah + a_goff[i]);
        pal[i] = *(const unsigned*)(Al + a_goff[i]);
        pbh[i] = *(const unsigned*)(Bh + b_goff[i]);
        pbl[i] = *(const unsigned*)(Bl + b_goff[i]);
    }

    for (int kk = 0; kk < K; kk += 32) {
        // store current chunk
#pragma unroll
        for (int i = 0; i < 8; i++) {
            sAh[a_soff[i]] = pah[i]; sAl[a_soff[i]] = pal[i];
            sBh[b_soff[i]] = pbh[i]; sBl[b_soff[i]] = pbl[i];
        }
        __syncthreads();

        // prefetch next chunk
        if (kk + 32 < K) {
            int kn = kk + 32;
#pragma unroll
            for (int i = 0; i < 8; i++) {
                pah[i] = *(const unsigned*)(Ah + a_goff[i] + kn);
                pal[i] = *(const unsigned*)(Al + a_goff[i] + kn);
                pbh[i] = *(const unsigned*)(Bh + b_goff[i] + kn);
                pbl[i] = *(const unsigned*)(Bl + b_goff[i] + kn);
            }
        }

        // compute (round-6 verbatim)
#pragma unroll
        for (int ks = 0; ks < 2; ks++) {
            unsigned bh[4][2], bl[4][2];
#pragma unroll
            for (int j = 0; j < 4; j++) {
                int base = (((wn * 4 + j) * 2 + ks) * 32 + ln) * 2;
                *(uint2*)bh[j] = *(const uint2*)&sBh[base];
                *(uint2*)bl[j] = *(const uint2*)&sBl[base];
            }
#pragma unroll
            for (int i = 0; i < 4; i++) {
                int abase = (((wm * 4 + i) * 2 + ks) * 32 + ln) * 4;
                unsigned ah[4], al[4];
                *(uint4*)ah = *(const uint4*)&sAh[abase];
                *(uint4*)al = *(const uint4*)&sAl[abase];
#pragma unroll
                for (int j = 0; j < 4; j++) {
                    mma16816(acc[i][j], ah, bh[j]);
                    mma16816(acc[i][j], ah, bl[j]);
                    mma16816(acc[i][j], al, bh[j]);
                }
            }
        }
        __syncthreads();
    }

    // ---- epilogue ----
    const int g = ln >> 2, t = ln & 3;
#pragma unroll
    for (int i = 0; i < 4; i++) {
        size_t row = m0 + wm * 64 + i * 16 + g;
#pragma unroll
        for (int j = 0; j < 4; j++) {
            size_t col = n0 + wn * 32 + j * 8 + t * 2;
            if (!SPLITOUT) {
                *(float2*)&Cf[row * ldc + col] =
                    make_float2(acc[i][j][0] * scale, acc[i][j][1] * scale);
                *(float2*)&Cf[(row + 8) * ldc + col] =
                    make_float2(acc[i][j][2] * scale, acc[i][j][3] * scale);
            } else {
                bf16 h0, l0, h1, l1;
                split1(acc[i][j][0] * scale, h0, l0);
                split1(acc[i][j][1] * scale, h1, l1);
                *(unsigned*)&Ch[row * ldc + col] = pack2(h0, h1);
                *(unsigned*)&Cl[row * ldc + col] = pack2(l0, l1);
                split1(acc[i][j][2] * scale, h0, l0);
                split1(acc[i][j][3] * scale, h1, l1);
                *(unsigned*)&Ch[(row + 8) * ldc + col] = pack2(h0, h1);
                *(unsigned*)&Cl[(row + 8) * ldc + col] = pack2(l0, l1);
            }
        }
    }
}

// ---------------------------------------------------------------------------
// FP32-INPUT NN GEMM — round-6 mma_gemm NN branch VERBATIM (proven on HW).
// C[M,N] = A[M,K] @ B[K,N]; GATHER on B's k rows. fp32 out.
// ---------------------------------------------------------------------------
template<bool GATHER>
__device__ __forceinline__ void nn_fp32(
    const float* __restrict__ A, int lda,
    const float* __restrict__ B, int ldb,
    float* __restrict__ C, int ldc,
    int K, int m0, int n0, float scale)
{
    __shared__ unsigned sAh[2048], sAl[2048], sBh[2048], sBl[2048];
    const int tid = threadIdx.x;
    const int ln  = tid & 31;
    const int warp = tid >> 5;
    const int wm = warp >> 2, wn = warp & 3;

    int a_soff[8], a_goff[8], b_soff[8], b_aux[8];
#pragma unroll
    for (int i = 0; i < 8; i++) {
        int linear = tid + 256 * i;
        int r = linear >> 4, c = (linear & 15) * 2;
        int rr = r & 15, cc = c & 15;
        a_soff[i] = (((r >> 4) * 2 + (c >> 4)) * 32
                     + (rr & 7) * 4 + ((cc & 7) >> 1)) * 4
                    + ((rr >> 3) | ((cc >> 3) << 1));
        a_goff[i] = (m0 + r) * lda + c;

        int kk = (linear >> 7) * 2, nn = linear & 127;
        int k16 = kk & 15;
        b_soff[i] = (((nn >> 3) * 2 + (kk >> 4)) * 32
                     + (nn & 7) * 4 + ((k16 & 7) >> 1)) * 2
                    + (k16 >> 3);
        b_aux[i] = n0 + nn;
    }

    float acc[4][4][4];
#pragma unroll
    for (int i = 0; i < 4; i++)
#pragma unroll
        for (int j = 0; j < 4; j++)
#pragma unroll
            for (int r = 0; r < 4; r++) acc[i][j][r] = 0.f;

    float2 pa[8], pb[8];

#pragma unroll
    for (int i = 0; i < 8; i++) pa[i] = *(const float2*)(A + a_goff[i]);
#pragma unroll
    for (int i = 0; i < 8; i++) {
        int kk = ((tid + 256 * i) >> 7) * 2;
        int r0 = kk, r1 = kk + 1;
        if (GATHER) {
            r0 = g_rooms[r0 >> 8] * ROOM + (r0 & 255);
            r1 = g_rooms[r1 >> 8] * ROOM + (r1 & 255);
        }
        pb[i].x = B[(size_t)r0 * ldb + b_aux[i]];
        pb[i].y = B[(size_t)r1 * ldb + b_aux[i]];
    }

    for (int kk = 0; kk < K; kk += 32) {
#pragma unroll
        for (int i = 0; i < 8; i++) {
            unsigned h, l;
            split2(pa[i], h, l);
            sAh[a_soff[i]] = h; sAl[a_soff[i]] = l;
            split2(pb[i], h, l);
            sBh[b_soff[i]] = h; sBl[b_soff[i]] = l;
        }
        __syncthreads();

        if (kk + 32 < K) {
            int kn = kk + 32;
#pragma unroll
            for (int i = 0; i < 8; i++) pa[i] = *(const float2*)(A + a_goff[i] + kn);
#pragma unroll
            for (int i = 0; i < 8; i++) {
                int kr = kn + ((tid + 256 * i) >> 7) * 2;
                int r0 = kr, r1 = kr + 1;
                if (GATHER) {
                    r0 = g_rooms[r0 >> 8] * ROOM + (r0 & 255);
                    r1 = g_rooms[r1 >> 8] * ROOM + (r1 & 255);
                }
                pb[i].x = B[(size_t)r0 * ldb + b_aux[i]];
                pb[i].y = B[(size_t)r1 * ldb + b_aux[i]];
            }
        }

#pragma unroll
        for (int ks = 0; ks < 2; ks++) {
            unsigned bh[4][2], bl[4][2];
#pragma unroll
            for (int j = 0; j < 4; j++) {
                int base = (((wn * 4 + j) * 2 + ks) * 32 + ln) * 2;
                *(uint2*)bh[j] = *(const uint2*)&sBh[base];
                *(uint2*)bl[j] = *(const uint2*)&sBl[base];
            }
#pragma unroll
            for (int i = 0; i < 4; i++) {
                int abase = (((wm * 4 + i) * 2 + ks) * 32 + ln) * 4;
                unsigned ah[4], al[4];
                *(uint4*)ah = *(const uint4*)&sAh[abase];
                *(uint4*)al = *(const uint4*)&sAl[abase];
#pragma unroll
                for (int j = 0; j < 4; j++) {
                    mma16816(acc[i][j], ah, bh[j]);
                    mma16816(acc[i][j], ah, bl[j]);
                    mma16816(acc[i][j], al, bh[j]);
                }
            }
        }
        __syncthreads();
    }

    const int g = ln >> 2, t = ln & 3;
#pragma unroll
    for (int i = 0; i < 4; i++) {
        size_t row = m0 + wm * 64 + i * 16 + g;
#pragma unroll
        for (int j = 0; j < 4; j++) {
            size_t col = n0 + wn * 32 + j * 8 + t * 2;
            *(float2*)&C[row * ldc + col] =
                make_float2(acc[i][j][0] * scale, acc[i][j][1] * scale);
            *(float2*)&C[(row + 8) * ldc + col] =
                make_float2(acc[i][j][2] * scale, acc[i][j][3] * scale);
        }
    }
}

// ---------------------------------------------------------------------------
// Kernels
// ---------------------------------------------------------------------------
__global__ void normalize_rooms_kernel(const int* __restrict__ w) {
    bool is64 = (w[1] == 0) && (w[3] == 0) && (w[5] == 0) && (w[7] == 0);
    for (int i = 0; i < 8; i++)
        g_rooms[i] = is64 ? w[2 * i] : w[i];
}

// Pre-split conversion. Destination plane pair selected IN DEVICE CODE
// (passing __device__ symbols as host-side kernel args silently targets the
// host shadow via ATS on GB300 — that was the round-8/9/10 bug).
__global__ __launch_bounds__(256) void conv_sel(const float* __restrict__ src,
                                                int which, int n4) {
    int i = blockIdx.x * 256 + threadIdx.x;
    if (i >= n4) return;
    bf16 *dh, *dl;
    if (which == 0)      { dh = g_Hh;  dl = g_Hl;  }
    else if (which == 1) { dh = g_QBh; dl = g_QBl; }
    else if (which == 2) { dh = g_KBh; dl = g_KBl; }
    else                 { dh = g_VBh; dl = g_VBl; }
    float4 v = ((const float4*)src)[i];
    bf16 h0, l0, h1, l1, h2, l2, h3, l3;
    split1(v.x, h0, l0); split1(v.y, h1, l1); split1(v.z, h2, l2); split1(v.w, h3, l3);
    ((uint2*)dh)[i] = make_uint2(pack2(h0, h1), pack2(h2, h3));
    ((uint2*)dl)[i] = make_uint2(pack2(l0, l1), pack2(l2, l3));
}

// Q projection (gathered rows of q_block planes) -> Q planes
__global__ __launch_bounds__(256) void k_qproj() {
    nt_planes<true, true>(g_Hh, g_Hl, H, g_QBh, g_QBl, H, H,
                          blockIdx.y * 128, blockIdx.x * 128, 1.f,
                          nullptr, g_Qh, g_Ql, H);
}
// K projection -> K planes
__global__ __launch_bounds__(256) void k_kproj() {
    nt_planes<false, true>(g_Hh, g_Hl, H, g_KBh, g_KBl, H, H,
                           blockIdx.y * 128, blockIdx.x * 128, 1.f,
                           nullptr, g_Kh, g_Kl, ROOM);
}
// V projection -> fp32 g_V (for round-6 AV path)
__global__ __launch_bounds__(256) void k_vproj() {
    nt_planes<false, false>(g_Hh, g_Hl, H, g_VBh, g_VBl, H, H,
                            blockIdx.y * 128, blockIdx.x * 128, 1.f,
                            g_V, nullptr, nullptr, ROOM);
}
// scores: lower-triangular tiles only
__global__ __launch_bounds__(256) void k_scores(float* __restrict__ W) {
    if (blockIdx.x > blockIdx.y) return;
    const int h = blockIdx.z;
    nt_planes<false, false>(g_Qh + h * HD, g_Ql + h * HD, H,
                            g_Kh + (h & 1) * HD, g_Kl + (h & 1) * HD, ROOM,
                            HD, blockIdx.y * 128, blockIdx.x * 128, SCALE,
                            W + (size_t)h * S * S, nullptr, nullptr, S);
}
// AV (round-6 NN path, causal-limited K)
__global__ __launch_bounds__(256) void k_av(const float* __restrict__ W) {
    const int h = blockIdx.z;
    const int m0 = blockIdx.y * 128;
    int Keff = m0 + 128;
    if (Keff > S) Keff = S;
    nn_fp32<false>(W + (size_t)h * S * S, S,
                   g_V + (size_t)(h & 1) * HD, ROOM,
                   g_A + (size_t)h * HD, H,
                   Keff, m0, 0, 1.0f);
}
// O projection (round-6 NN path, gathered k rows of ob)
__global__ __launch_bounds__(256) void k_oproj(const float* __restrict__ ob,
                                               float* __restrict__ out) {
    nn_fp32<true>(g_A, H, ob, H, out, H, H,
                  blockIdx.y * 128, blockIdx.x * 128, 1.0f);
}

// ---------------------------------------------------------------------------
// Softmax per (head, q-row): register-cached, 1 read + 1 write.
// ---------------------------------------------------------------------------
__global__ __launch_bounds__(256) void softmax_kernel(float* __restrict__ W) {
    const int q = blockIdx.x, h = blockIdx.y;
    float* row = W + ((size_t)h * S + q) * S;
    const int L = q + 1;
    const int tid = threadIdx.x;
    __shared__ float sh[8];

    float v[8];
#pragma unroll
    for (int i = 0; i < 8; i++) {
        int k = tid + i * 256;
        v[i] = (k < L) ? row[k] : -3.4e38f;
    }
    float m = v[0];
#pragma unroll
    for (int i = 1; i < 8; i++) m = fmaxf(m, v[i]);
#pragma unroll
    for (int o = 16; o > 0; o >>= 1) m = fmaxf(m, __shfl_xor_sync(0xffffffffu, m, o));
    if ((tid & 31) == 0) sh[tid >> 5] = m;
    __syncthreads();
    float mm = sh[0];
#pragma unroll
    for (int i = 1; i < 8; i++) mm = fmaxf(mm, sh[i]);
    __syncthreads();

    float e[8], ssum = 0.f;
#pragma unroll
    for (int i = 0; i < 8; i++) {
        int k = tid + i * 256;
        e[i] = (k < L) ? __expf(v[i] - mm) : 0.f;
        ssum += e[i];
    }
#pragma unroll
    for (int o = 16; o > 0; o >>= 1) ssum += __shfl_xor_sync(0xffffffffu, ssum, o);
    if ((tid & 31) == 0) sh[tid >> 5] = ssum;
    __syncthreads();
    float tot = 0.f;
#pragma unroll
    for (int i = 0; i < 8; i++) tot += sh[i];
    const float inv = 1.0f / tot;

#pragma unroll
    for (int i = 0; i < 8; i++) {
        int k = tid + i * 256;
        row[k] = e[i] * inv;   // exact 0 beyond the diagonal
    }
}

// ---------------------------------------------------------------------------
// Launch
// ---------------------------------------------------------------------------
extern "C" void kernel_launch(void* const* d_in, const int* in_sizes, int n_in,
                              void* d_out, int out_size)
{
    const float* hidden = (const float*)d_in[0];
    const float* qb     = (const float*)d_in[1];
    const float* kb     = (const float*)d_in[2];
    const float* vb     = (const float*)d_in[3];
    const float* ob     = (const float*)d_in[4];
    const int*   rooms_raw = (const int*)d_in[5];

    float* out   = (float*)d_out;
    float* o_out = out;                      // [S, H]
    float* W     = out + (size_t)S * H;      // [NH, S, S]

    (void)in_sizes; (void)n_in; (void)out_size;

    // 0) canonicalize rooms + pre-split fp32 operands to bf16 hi/lo planes
    normalize_rooms_kernel<<<1, 1>>>(rooms_raw);
    conv_sel<<<(S * H / 4) / 256, 256>>>(hidden, 0, S * H / 4);
    conv_sel<<<(H * H / 4) / 256, 256>>>(qb, 1, H * H / 4);
    conv_sel<<<(ROOM * H / 4) / 256, 256>>>(kb, 2, ROOM * H / 4);
    conv_sel<<<(ROOM * H / 4) / 256, 256>>>(vb, 3, ROOM * H / 4);

    // 1) projections
    k_qproj<<<dim3(16, 16), 256>>>();
    k_kproj<<<dim3(2, 16),  256>>>();
    k_vproj<<<dim3(2, 16),  256>>>();

    // 2) scores (lower-triangular tiles only)
    k_scores<<<dim3(16, 16, NH), 256>>>(W);

    // 3) softmax
    softmax_kernel<<<dim3(S, NH), 256>>>(W);

    // 4) AV
    k_av<<<dim3(1, 16, NH), 256>>>(W);

    // 5) O projection
    k_oproj<<<dim3(16, 16), 256>>>(ob, o_out);
}

// round 12
// speedup vs baseline: 1.4981x; 1.4981x over previous
#include <cuda_runtime.h>
#include <cuda_bf16.h>
#include <cstdint>
#include <math.h>

#define S   2048
#define H   2048
#define ROOM 256
#define NH  16
#define HD  128
#define SCALE 0.08838834764831845f  // 1/sqrt(128)

typedef __nv_bfloat16 bf16;

// ---------------- device globals (allocation-free scratch, ~344MB) ---------
__device__ __align__(16) bf16 g_Hh [(size_t)S*H],    g_Hl [(size_t)S*H];     // hidden planes
__device__ __align__(16) bf16 g_QBh[(size_t)H*H],    g_QBl[(size_t)H*H];     // q_block planes (ungathered)
__device__ __align__(16) bf16 g_KBh[(size_t)ROOM*H], g_KBl[(size_t)ROOM*H];  // k_block planes
__device__ __align__(16) bf16 g_VBh[(size_t)ROOM*H], g_VBl[(size_t)ROOM*H];  // v_block planes
__device__ __align__(16) bf16 g_OBth[(size_t)H*H],   g_OBtl[(size_t)H*H];    // o_active^T [n][t]
__device__ __align__(16) bf16 g_Qh [(size_t)S*H],    g_Ql [(size_t)S*H];     // Q projection planes
__device__ __align__(16) bf16 g_Kh [(size_t)S*ROOM], g_Kl [(size_t)S*ROOM];  // k_one planes
__device__ __align__(16) bf16 g_Vth[(size_t)ROOM*S], g_Vtl[(size_t)ROOM*S];  // v_one^T [d][s]
__device__ __align__(16) bf16 g_Wh [(size_t)NH*S*S], g_Wl [(size_t)NH*S*S];  // softmaxed W planes
__device__ __align__(16) bf16 g_Ah [(size_t)S*H],    g_Al [(size_t)S*H];     // attn_out planes
__device__ int g_rooms[8];

// ---------------- helpers ----------------
__device__ __forceinline__ uint32_t smem_u32(const void* p) {
    uint32_t a;
    asm("{ .reg .u64 t; cvta.to.shared.u64 t, %1; cvt.u32.u64 %0, t; }" : "=r"(a) : "l"(p));
    return a;
}
__device__ __forceinline__ void split1(float x, bf16& h, bf16& l) {
    h = __float2bfloat16_rn(x);
    l = __float2bfloat16_rn(x - __bfloat162float(h));
}
__device__ __forceinline__ unsigned pack2(bf16 a, bf16 b) {
    return ((unsigned)__bfloat16_as_ushort(b) << 16) | __bfloat16_as_ushort(a);
}
__device__ __forceinline__ void mma16816(float* d, const unsigned* a, const unsigned* b)
{
    asm volatile(
        "mma.sync.aligned.m16n8k16.row.col.f32.bf16.bf16.f32 "
        "{%0,%1,%2,%3}, {%4,%5,%6,%7}, {%8,%9}, {%0,%1,%2,%3};\n"
        : "+f"(d[0]), "+f"(d[1]), "+f"(d[2]), "+f"(d[3])
        : "r"(a[0]), "r"(a[1]), "r"(a[2]), "r"(a[3]), "r"(b[0]), "r"(b[1]));
}
__device__ __forceinline__ void ldm_x4(unsigned &r0, unsigned &r1, unsigned &r2, unsigned &r3,
                                       uint32_t addr)
{
    asm volatile("ldmatrix.sync.aligned.m8n8.x4.shared.b16 {%0,%1,%2,%3}, [%4];"
                 : "=r"(r0), "=r"(r1), "=r"(r2), "=r"(r3) : "r"(addr));
}
__device__ __forceinline__ void cpasync16(uint32_t dst, const void* src) {
    asm volatile("cp.async.cg.shared.global [%0], [%1], 16;" :: "r"(dst), "l"(src) : "memory");
}

// ---------------------------------------------------------------------------
// cp.async + ldmatrix NT GEMM core on pre-split bf16 planes.
// C[128,128] = A[M,K] @ B[N,K]^T, 3-term split (hh+hl+lh), fp32 accum.
// 128 threads, 4 warps (2x2 grid of 64x64 warp tiles), BK=32, double-buffered.
// Smem layout per operand: 128 rows x 128B; row = [hi k0..31 | lo k0..31],
// 8x16B units, swizzled u' = u ^ (row&7). One buffer = A 16KB + B 16KB.
// GATHER: 256-row-block gather on B's n rows. SPLITOUT: write bf16 planes.
// ---------------------------------------------------------------------------
#define DSMEM (2 * 32768)

template<bool GATHER, bool SPLITOUT>
__device__ __forceinline__ void gemm_core(
    const bf16* __restrict__ Ah_, const bf16* __restrict__ Al_, int lda,
    const bf16* __restrict__ Bh_, const bf16* __restrict__ Bl_, int ldb,
    int nch, int m0, int n0, float scale,
    float* __restrict__ Cf, bf16* __restrict__ Ch, bf16* __restrict__ Cl, int ldc)
{
    extern __shared__ char smemraw[];
    const uint32_t sbase = smem_u32(smemraw);
    const int tid = threadIdx.x;          // 0..127
    const int l = tid & 31, w = tid >> 5;
    const int wm = w >> 1, wn = w & 1;

    // ---- cp.async staging precompute ----
    // per thread: plane = (tid>>2)&1, k-octet = tid&3, base row r0 = tid>>3;
    // covers rows r0 + 16*i, i = 0..7, for BOTH operands (16 cp.async/chunk).
    const int plane = (tid >> 2) & 1;
    const int k8    = tid & 3;
    const int r0    = tid >> 3;                       // 0..15
    const int swu   = (tid & 7) ^ (r0 & 7);           // row&7 invariant under +16
    const bf16* Asrc = (plane ? Al_ : Ah_) + (size_t)(m0 + r0) * lda + k8 * 8;
    int brow = n0 + r0;
    if (GATHER) brow = g_rooms[n0 >> 8] * ROOM + ((n0 + r0) & 255);
    const bf16* Bsrc = (plane ? Bl_ : Bh_) + (size_t)brow * ldb + k8 * 8;
    const uint32_t dA0 = sbase + r0 * 128 + swu * 16;
    const uint32_t dB0 = dA0 + 16384;

    auto stage = [&](int kk, int buf) {
        const uint32_t boff = buf * 32768;
        const bf16* as = Asrc + kk;
        const bf16* bs = Bsrc + kk;
#pragma unroll
        for (int i = 0; i < 8; i++) {
            cpasync16(dA0 + boff + i * 2048, as + (size_t)i * 16 * lda);
            cpasync16(dB0 + boff + i * 2048, bs + (size_t)i * 16 * ldb);
        }
        asm volatile("cp.async.commit_group;" ::: "memory");
    };

    float acc[4][8][4];
#pragma unroll
    for (int i = 0; i < 4; i++)
#pragma unroll
        for (int j = 0; j < 8; j++)
#pragma unroll
            for (int r = 0; r < 4; r++) acc[i][j][r] = 0.f;

    stage(0, 0);
    stage(32, 1);       // all call sites have nch >= 4

    for (int c = 0; c < nch; c++) {
        if (c + 1 < nch) asm volatile("cp.async.wait_group 1;" ::: "memory");
        else             asm volatile("cp.async.wait_group 0;" ::: "memory");
        __syncthreads();
        const uint32_t Ab = sbase + (c & 1) * 32768;
        const uint32_t Bb = Ab + 16384;
        const int mi = l >> 3;     // ldmatrix matrix index 0..3
        const int r8 = l & 7;      // row within 8x8 matrix

#pragma unroll
        for (int ks = 0; ks < 2; ks++) {
            // B fragments: 8 n8-blocks, hi+lo. x4 loads two j-blocks.
            unsigned bh[8][2], bl[8][2];
#pragma unroll
            for (int jp = 0; jp < 4; jp++) {
                int nl = wn * 64 + jp * 16 + (mi >> 1) * 8 + r8;
                int uh = (    ks * 2 + (mi & 1)) ^ (nl & 7);
                int ul = (4 + ks * 2 + (mi & 1)) ^ (nl & 7);
                ldm_x4(bh[2*jp][0], bh[2*jp][1], bh[2*jp+1][0], bh[2*jp+1][1],
                       Bb + nl * 128 + uh * 16);
                ldm_x4(bl[2*jp][0], bl[2*jp][1], bl[2*jp+1][0], bl[2*jp+1][1],
                       Bb + nl * 128 + ul * 16);
            }
#pragma unroll
            for (int i = 0; i < 4; i++) {
                int ml = wm * 64 + i * 16 + (mi & 1) * 8 + r8;
                int uh = (    ks * 2 + (mi >> 1)) ^ (ml & 7);
                int ul = (4 + ks * 2 + (mi >> 1)) ^ (ml & 7);
                unsigned ah[4], al[4];
                ldm_x4(ah[0], ah[1], ah[2], ah[3], Ab + ml * 128 + uh * 16);
                ldm_x4(al[0], al[1], al[2], al[3], Ab + ml * 128 + ul * 16);
#pragma unroll
                for (int j = 0; j < 8; j++) {
                    mma16816(acc[i][j], ah, bh[j]);
                    mma16816(acc[i][j], ah, bl[j]);
                    mma16816(acc[i][j], al, bh[j]);
                }
            }
        }
        __syncthreads();
        if (c + 2 < nch) stage((c + 2) * 32, c & 1);
    }

    // ---- epilogue ----
    const int g = l >> 2, t = l & 3;
#pragma unroll
    for (int i = 0; i < 4; i++) {
        size_t row = m0 + wm * 64 + i * 16 + g;
#pragma unroll
        for (int j = 0; j < 8; j++) {
            size_t col = n0 + wn * 64 + j * 8 + t * 2;
            if (!SPLITOUT) {
                *(float2*)&Cf[row * ldc + col] =
                    make_float2(acc[i][j][0] * scale, acc[i][j][1] * scale);
                *(float2*)&Cf[(row + 8) * ldc + col] =
                    make_float2(acc[i][j][2] * scale, acc[i][j][3] * scale);
            } else {
                bf16 h0, l0, h1, l1;
                split1(acc[i][j][0] * scale, h0, l0);
                split1(acc[i][j][1] * scale, h1, l1);
                *(unsigned*)&Ch[row * ldc + col] = pack2(h0, h1);
                *(unsigned*)&Cl[row * ldc + col] = pack2(l0, l1);
                split1(acc[i][j][2] * scale, h0, l0);
                split1(acc[i][j][3] * scale, h1, l1);
                *(unsigned*)&Ch[(row + 8) * ldc + col] = pack2(h0, h1);
                *(unsigned*)&Cl[(row + 8) * ldc + col] = pack2(l0, l1);
            }
        }
    }
}

// ---------------------------------------------------------------------------
// GEMM wrapper kernels (device-global pointers resolved in device code only)
// ---------------------------------------------------------------------------
__global__ __launch_bounds__(128, 2) void k_qproj() {
    gemm_core<true, true>(g_Hh, g_Hl, H, g_QBh, g_QBl, H, 64,
                          blockIdx.y * 128, blockIdx.x * 128, 1.f,
                          nullptr, g_Qh, g_Ql, H);
}
__global__ __launch_bounds__(128, 2) void k_kproj() {
    gemm_core<false, true>(g_Hh, g_Hl, H, g_KBh, g_KBl, H, 64,
                           blockIdx.y * 128, blockIdx.x * 128, 1.f,
                           nullptr, g_Kh, g_Kl, ROOM);
}
// Vt[d, s] = vb[d,:] . hidden[s,:]
__global__ __launch_bounds__(128, 2) void k_vprojT() {
    gemm_core<false, true>(g_VBh, g_VBl, H, g_Hh, g_Hl, H, 64,
                           blockIdx.y * 128, blockIdx.x * 128, 1.f,
                           nullptr, g_Vth, g_Vtl, S);
}
__global__ __launch_bounds__(128, 2) void k_scores(float* __restrict__ W) {
    if (blockIdx.x > blockIdx.y) return;   // strictly above diagonal
    const int h = blockIdx.z;
    gemm_core<false, false>(g_Qh + h * HD, g_Ql + h * HD, H,
                            g_Kh + (h & 1) * HD, g_Kl + (h & 1) * HD, ROOM,
                            4, blockIdx.y * 128, blockIdx.x * 128, SCALE,
                            W + (size_t)h * S * S, nullptr, nullptr, S);
}
// A[q, h*128+d] = sum_k W[q,k] Vt[d,k]  (K causally limited to (by+1)*128)
__global__ __launch_bounds__(128, 2) void k_av() {
    const int h = blockIdx.z, by = blockIdx.y;
    gemm_core<false, true>(g_Wh + (size_t)h * S * S, g_Wl + (size_t)h * S * S, S,
                           g_Vth + (size_t)(h & 1) * 128 * S,
                           g_Vtl + (size_t)(h & 1) * 128 * S, S,
                           (by + 1) * 4, by * 128, 0, 1.f,
                           nullptr, g_Ah + h * HD, g_Al + h * HD, H);
}
__global__ __launch_bounds__(128, 2) void k_oproj(float* __restrict__ out) {
    gemm_core<false, false>(g_Ah, g_Al, H, g_OBth, g_OBtl, H, 64,
                            blockIdx.y * 128, blockIdx.x * 128, 1.f,
                            out, nullptr, nullptr, H);
}

// ---------------------------------------------------------------------------
// Pre-convert kernels
// ---------------------------------------------------------------------------
__global__ void normalize_rooms_kernel(const int* __restrict__ w) {
    bool is64 = (w[1] == 0) && (w[3] == 0) && (w[5] == 0) && (w[7] == 0);
    for (int i = 0; i < 8; i++)
        g_rooms[i] = is64 ? w[2 * i] : w[i];
}

// destination plane pair selected in DEVICE code (host-passed __device__
// symbols silently hit the host shadow via ATS on GB300)
__global__ __launch_bounds__(256) void conv_sel(const float* __restrict__ src,
                                                int which, int n4) {
    int i = blockIdx.x * 256 + threadIdx.x;
    if (i >= n4) return;
    bf16 *dh, *dl;
    if (which == 0)      { dh = g_Hh;  dl = g_Hl;  }
    else if (which == 1) { dh = g_QBh; dl = g_QBl; }
    else if (which == 2) { dh = g_KBh; dl = g_KBl; }
    else                 { dh = g_VBh; dl = g_VBl; }
    float4 v = ((const float4*)src)[i];
    bf16 h0, l0, h1, l1, h2, l2, h3, l3;
    split1(v.x, h0, l0); split1(v.y, h1, l1); split1(v.z, h2, l2); split1(v.w, h3, l3);
    ((uint2*)dh)[i] = make_uint2(pack2(h0, h1), pack2(h2, h3));
    ((uint2*)dl)[i] = make_uint2(pack2(l0, l1), pack2(l2, l3));
}

// transpose + gather: OBt[n][t] = ob[rooms[t>>8]*256 + (t&255)][n]
__global__ void conv_obt(const float* __restrict__ ob) {
    __shared__ float s[32][33];
    int t0 = blockIdx.y * 32, n0v = blockIdx.x * 32;
    int tx = threadIdx.x, ty = threadIdx.y;   // (32, 8)
#pragma unroll
    for (int i = 0; i < 4; i++) {
        int r = ty + i * 8;
        int sr = g_rooms[(t0 + r) >> 8] * ROOM + ((t0 + r) & 255);
        s[r][tx] = ob[(size_t)sr * H + n0v + tx];
    }
    __syncthreads();
#pragma unroll
    for (int i = 0; i < 4; i++) {
        int r = ty + i * 8;
        float v = s[tx][r];
        bf16 h, l;
        split1(v, h, l);
        g_OBth[(size_t)(n0v + r) * H + t0 + tx] = h;
        g_OBtl[(size_t)(n0v + r) * H + t0 + tx] = l;
    }
}

// ---------------------------------------------------------------------------
// Softmax per (head, q-row): one read, writes fp32 W row (full) + bf16 hi/lo
// planes zero-filled to the q-BLOCK boundary ((q/128+1)*128) so AV's K range
// reads exact zeros.
// ---------------------------------------------------------------------------
__global__ __launch_bounds__(256) void softmax_kernel(float* __restrict__ W) {
    const int q = blockIdx.x, h = blockIdx.y;
    float* row = W + ((size_t)h * S + q) * S;
    unsigned* rh = (unsigned*)(g_Wh + ((size_t)h * S + q) * S);
    unsigned* rl = (unsigned*)(g_Wl + ((size_t)h * S + q) * S);
    const int L = q + 1;
    const int Lpad = ((q >> 7) + 1) << 7;
    const int tid = threadIdx.x;
    __shared__ float sh[8];

    float2 v[4];
    float m = -3.4e38f;
#pragma unroll
    for (int i = 0; i < 4; i++) {
        int p = tid + i * 256;
        float2 x = ((const float2*)row)[p];
        int k0 = p * 2;
        v[i].x = (k0     < L) ? x.x : -3.4e38f;
        v[i].y = (k0 + 1 < L) ? x.y : -3.4e38f;
        m = fmaxf(m, fmaxf(v[i].x, v[i].y));
    }
#pragma unroll
    for (int o = 16; o > 0; o >>= 1) m = fmaxf(m, __shfl_xor_sync(0xffffffffu, m, o));
    if ((tid & 31) == 0) sh[tid >> 5] = m;
    __syncthreads();
    float mm = sh[0];
#pragma unroll
    for (int i = 1; i < 8; i++) mm = fmaxf(mm, sh[i]);
    __syncthreads();

    float ex[4], ey[4], ssum = 0.f;
#pragma unroll
    for (int i = 0; i < 4; i++) {
        int k0 = (tid + i * 256) * 2;
        ex[i] = (k0     < L) ? __expf(v[i].x - mm) : 0.f;
        ey[i] = (k0 + 1 < L) ? __expf(v[i].y - mm) : 0.f;
        ssum += ex[i] + ey[i];
    }
#pragma unroll
    for (int o = 16; o > 0; o >>= 1) ssum += __shfl_xor_sync(0xffffffffu, ssum, o);
    if ((tid & 31) == 0) sh[tid >> 5] = ssum;
    __syncthreads();
    float tot = 0.f;
#pragma unroll
    for (int i = 0; i < 8; i++) tot += sh[i];
    const float inv = 1.0f / tot;

#pragma unroll
    for (int i = 0; i < 4; i++) {
        int p = tid + i * 256;
        int k0 = p * 2;
        float wx = ex[i] * inv, wy = ey[i] * inv;
        ((float2*)row)[p] = make_float2(wx, wy);
        if (k0 < Lpad) {
            bf16 h0, l0, h1, l1;
            split1(wx, h0, l0); split1(wy, h1, l1);
            rh[p] = pack2(h0, h1);
            rl[p] = pack2(l0, l1);
        }
    }
}

// ---------------------------------------------------------------------------
// Launch
// ---------------------------------------------------------------------------
extern "C" void kernel_launch(void* const* d_in, const int* in_sizes, int n_in,
                              void* d_out, int out_size)
{
    const float* hidden = (const float*)d_in[0];
    const float* qb     = (const float*)d_in[1];
    const float* kb     = (const float*)d_in[2];
    const float* vb     = (const float*)d_in[3];
    const float* ob     = (const float*)d_in[4];
    const int*   rooms_raw = (const int*)d_in[5];

    float* out   = (float*)d_out;
    float* o_out = out;                      // [S, H]
    float* W     = out + (size_t)S * H;      // [NH, S, S]

    (void)in_sizes; (void)n_in; (void)out_size;

    cudaFuncSetAttribute(k_qproj,  cudaFuncAttributeMaxDynamicSharedMemorySize, DSMEM);
    cudaFuncSetAttribute(k_kproj,  cudaFuncAttributeMaxDynamicSharedMemorySize, DSMEM);
    cudaFuncSetAttribute(k_vprojT, cudaFuncAttributeMaxDynamicSharedMemorySize, DSMEM);
    cudaFuncSetAttribute(k_scores, cudaFuncAttributeMaxDynamicSharedMemorySize, DSMEM);
    cudaFuncSetAttribute(k_av,     cudaFuncAttributeMaxDynamicSharedMemorySize, DSMEM);
    cudaFuncSetAttribute(k_oproj,  cudaFuncAttributeMaxDynamicSharedMemorySize, DSMEM);

    // 0) canonicalize rooms + pre-split operands to bf16 hi/lo planes
    normalize_rooms_kernel<<<1, 1>>>(rooms_raw);
    conv_sel<<<(S * H / 4) / 256, 256>>>(hidden, 0, S * H / 4);
    conv_sel<<<(H * H / 4) / 256, 256>>>(qb, 1, H * H / 4);
    conv_sel<<<(ROOM * H / 4) / 256, 256>>>(kb, 2, ROOM * H / 4);
    conv_sel<<<(ROOM * H / 4) / 256, 256>>>(vb, 3, ROOM * H / 4);
    conv_obt<<<dim3(H / 32, H / 32), dim3(32, 8)>>>(ob);

    // 1) projections
    k_qproj <<<dim3(16, 16), 128, DSMEM>>>();
    k_kproj <<<dim3(2, 16),  128, DSMEM>>>();
    k_vprojT<<<dim3(16, 2),  128, DSMEM>>>();

    // 2) scores (lower-triangular tiles only)
    k_scores<<<dim3(16, 16, NH), 128, DSMEM>>>(W);

    // 3) softmax (fp32 W + bf16 planes)
    softmax_kernel<<<dim3(S, NH), 256>>>(W);

    // 4) AV
    k_av<<<dim3(1, 16, NH), 128, DSMEM>>>();

    // 5) O projection
    k_oproj<<<dim3(16, 16), 128, DSMEM>>>(o_out);
}